// round 14
// baseline (speedup 1.0000x reference)
#include <cuda_runtime.h>

// HexaToParallelogram: out[bs, q, r] = hexa[bs, pix(q,r)] for valid hex cells
// (|q+r| <= 18), 0.0 for corner cells. In: [32768, 1039] fp32 (first 1027 used),
// out: [32768, 1369] fp32.
//
// Direct gmem->gmem copy. Supertile = 4 bs-rows = 5476 floats = 1369 float4s
// (1369 % 4 == 1 makes the alignment pattern repeat every 4 rows). Each thread
// owns one float4 slot, resolves its (src, valid, contiguity) tuple ONCE, then
// grid-strides over supertiles with pointer bumps.
//
// Load shape: within a q-row the gather is affine (src = j + D), so a slot's 4
// sources are consecutive floats. Instead of 4 LDG.32 (lane-stride 16 B -> each
// load spans 512 B / 16 sectors -> ~16 L1tex wavefronts per warp-iter), issue
// 2 aligned LDG.128 covering the 8-float window [off0 & ~3, +8) and funnel-
// select with loop-invariant sel = off0 & 3 (~10 wavefronts). Rare row-straddle
// or corner elements fall back to predicated scalar loads / zero.

#define W          37
#define CELLS      1369              // 37*37
#define IN_STRIDE  1039
#define TPB        512
#define SLOTS      1369              // float4 slots per supertile
#define GROUPS     512               // concurrent supertile streams

__device__ __forceinline__ int src_index(int j) {
    int qi = j / W;              // constant divisor -> mulhi
    int ri = j - qi * W;
    int s = qi + ri;
    if (s < 18 || s > 54) return -1;   // padding corner
    if (qi <= 18) {
        return 19 * qi + (qi * (qi - 1)) / 2 + (ri + qi - 18);
    } else {
        int q = qi - 18;
        return 495 + 37 * q - (q * (q - 1)) / 2 + ri;
    }
}

// pick w[sel] from 4 candidates, sel in 0..3 given as two loop-invariant bools
__device__ __forceinline__ float pick4(float a, float b, float c, float d,
                                       bool s_hi, bool s_lo) {
    float lo = s_lo ? b : a;
    float hi = s_lo ? d : c;
    return s_hi ? hi : lo;
}

__global__ void __launch_bounds__(TPB)
hexa_direct_kernel(const float* __restrict__ hexa,
                   float* __restrict__ out,
                   int n_super) {
    int t = blockIdx.x * TPB + threadIdx.x;
    if (t >= SLOTS * GROUPS) return;
    int v = t % SLOTS;           // float4 slot within supertile (one-time div)
    int s = t / SLOTS;           // starting supertile
    if (s >= n_super) return;

    // One-time setup: resolve the 4 elements of this slot.
    int f  = 4 * v;              // flat float index in supertile [0, 5476)
    int lr = f / CELLS;          // row within supertile (0..3)
    int j0 = f - lr * CELLS;

    int  off[4];                 // input offset within supertile (floats)
    bool val[4];
    #pragma unroll
    for (int e = 0; e < 4; e++) {
        int j = j0 + e;
        int lrr = lr;
        if (j >= CELLS) { j -= CELLS; lrr++; }
        int src = src_index(j);
        val[e] = (src >= 0);
        off[e] = lrr * IN_STRIDE + (src >= 0 ? src : 0);
    }
    // contiguity with element 0 (true for the vast majority of slots)
    bool c1 = val[1] && (off[1] == off[0] + 1);
    bool c2 = val[2] && (off[2] == off[0] + 2);
    bool c3 = val[3] && (off[3] == off[0] + 3);

    const int A   = off[0] >> 2;       // aligned float4 window start
    const bool s_hi = (off[0] & 2) != 0;
    const bool s_lo = (off[0] & 1) != 0;

    const float* __restrict__ ip = hexa + (size_t)s * (4 * IN_STRIDE);
    float4* __restrict__ op = (float4*)(out + (size_t)s * (4 * CELLS)) + v;

    const size_t ip_step = (size_t)GROUPS * (4 * IN_STRIDE);  // % 4 == 0
    const size_t op_step = (size_t)GROUPS * CELLS;            // in float4s

    #pragma unroll 2
    for (; s < n_super; s += GROUPS) {
        const float4* ip4 = (const float4*)ip;
        float4 wa = __ldg(ip4 + A);
        float4 wb = __ldg(ip4 + A + 1);
        // window floats w0..w6 (w7 never needed: sel<=3, e<=3 -> idx<=6)
        float4 o;
        o.x = pick4(wa.x, wa.y, wa.z, wa.w, s_hi, s_lo);
        o.y = pick4(wa.y, wa.z, wa.w, wb.x, s_hi, s_lo);
        o.z = pick4(wa.z, wa.w, wb.x, wb.y, s_hi, s_lo);
        o.w = pick4(wa.w, wb.x, wb.y, wb.z, s_hi, s_lo);
        // fixups (loop-invariant predicates -> predicated scalar LDG, rare)
        if (!val[0]) o.x = 0.0f;
        if (!c1) o.y = val[1] ? __ldg(ip + off[1]) : 0.0f;
        if (!c2) o.z = val[2] ? __ldg(ip + off[2]) : 0.0f;
        if (!c3) o.w = val[3] ? __ldg(ip + off[3]) : 0.0f;
        *op = o;
        ip += ip_step;
        op += op_step;
    }
}

// Fallback scalar kernel for any tail rows (total_rows % 4 != 0)
__global__ void __launch_bounds__(256)
hexa_tail_kernel(const float* __restrict__ hexa,
                 float* __restrict__ out,
                 int row_start, int total_rows) {
    int j = blockIdx.x * 256 + threadIdx.x;
    if (j >= CELLS) return;
    int src = src_index(j);
    for (int row = row_start + blockIdx.y; row < total_rows; row += gridDim.y) {
        float v = (src >= 0) ? __ldg(hexa + (size_t)row * IN_STRIDE + src) : 0.0f;
        out[(size_t)row * CELLS + j] = v;
    }
}

extern "C" void kernel_launch(void* const* d_in, const int* in_sizes, int n_in,
                              void* d_out, int out_size) {
    const float* hexa = (const float*)d_in[0];
    float* out = (float*)d_out;

    int total_rows = out_size / CELLS;       // 32768
    int n_super = total_rows / 4;            // 8192
    if (n_super > 0) {
        int threads = SLOTS * GROUPS;            // 700,928
        int blocks = (threads + TPB - 1) / TPB;  // 1369
        hexa_direct_kernel<<<blocks, TPB>>>(hexa, out, n_super);
    }
    int done = n_super * 4;
    if (done < total_rows) {
        dim3 grid((CELLS + 255) / 256, total_rows - done);
        hexa_tail_kernel<<<grid, 256>>>(hexa, out, done, total_rows);
    }
}

// round 15
// speedup vs baseline: 1.1366x; 1.1366x over previous
#include <cuda_runtime.h>

// HexaToParallelogram: out[bs, q, r] = hexa[bs, pix(q,r)] for valid hex cells
// (|q+r| <= 18), 0.0 for corner cells. In: [32768, 1039] fp32 (first 1027 used),
// out: [32768, 1369] fp32.
//
// FINAL (converged over 14 measured rounds): direct gmem->gmem gather.
// Since 1369 % 4 == 1, output float4 alignment repeats every 4 bs-rows
// (supertile = 4*1369 = 5476 floats = 1369 float4s). Each thread owns one
// float4 slot v of the supertile, computes its (row-in-supertile, src, valid)
// tuple ONCE, then grid-strides over supertiles with pure pointer bumps:
//   4 predicated LDG.32 (L1-cached; the interleaved-sector loads dedup in L1)
//   1 STG.128 per iteration.
// Measured: ~48 us kernel, ~5.5 TB/s effective HBM — at the practical mixed
// read/write-stream ceiling for this access shape (ablations over cache hints,
// unroll depth, grid size/shape, iteration order, CTA shape, and load
// vectorization were all neutral or worse).

#define W          37
#define CELLS      1369              // 37*37
#define IN_STRIDE  1039
#define TPB        256
#define SLOTS      1369              // float4 slots per supertile
#define GROUPS     512               // concurrent supertile streams

__device__ __forceinline__ int src_index(int j) {
    int qi = j / W;              // constant divisor -> mulhi
    int ri = j - qi * W;
    int s = qi + ri;
    if (s < 18 || s > 54) return -1;   // padding corner
    if (qi <= 18) {
        return 19 * qi + (qi * (qi - 1)) / 2 + (ri + qi - 18);
    } else {
        int q = qi - 18;
        return 495 + 37 * q - (q * (q - 1)) / 2 + ri;
    }
}

__global__ void __launch_bounds__(TPB)
hexa_direct_kernel(const float* __restrict__ hexa,
                   float* __restrict__ out,
                   int n_super) {
    int t = blockIdx.x * TPB + threadIdx.x;
    if (t >= SLOTS * GROUPS) return;
    int v = t % SLOTS;           // float4 slot within supertile (one-time div)
    int s = t / SLOTS;           // starting supertile
    if (s >= n_super) return;

    // One-time setup: resolve the 4 elements of this slot.
    int f  = 4 * v;              // flat float index in supertile [0, 5476)
    int lr = f / CELLS;          // row within supertile (0..3)
    int j0 = f - lr * CELLS;

    int  off[4];                 // input offset within supertile (floats)
    bool val[4];
    #pragma unroll
    for (int e = 0; e < 4; e++) {
        int j = j0 + e;
        int lrr = lr;
        if (j >= CELLS) { j -= CELLS; lrr++; }
        int src = src_index(j);
        val[e] = (src >= 0);
        off[e] = lrr * IN_STRIDE + (src >= 0 ? src : 0);
    }

    const float* __restrict__ ip = hexa + (size_t)s * (4 * IN_STRIDE);
    float4* __restrict__ op = (float4*)(out + (size_t)s * (4 * CELLS)) + v;

    const size_t ip_step = (size_t)GROUPS * (4 * IN_STRIDE);
    const size_t op_step = (size_t)GROUPS * CELLS;   // in float4s

    #pragma unroll 2
    for (; s < n_super; s += GROUPS) {
        float4 o;
        o.x = val[0] ? __ldg(ip + off[0]) : 0.0f;
        o.y = val[1] ? __ldg(ip + off[1]) : 0.0f;
        o.z = val[2] ? __ldg(ip + off[2]) : 0.0f;
        o.w = val[3] ? __ldg(ip + off[3]) : 0.0f;
        *op = o;
        ip += ip_step;
        op += op_step;
    }
}

// Fallback scalar kernel for any tail rows (total_rows % 4 != 0)
__global__ void __launch_bounds__(TPB)
hexa_tail_kernel(const float* __restrict__ hexa,
                 float* __restrict__ out,
                 int row_start, int total_rows) {
    int j = blockIdx.x * TPB + threadIdx.x;
    if (j >= CELLS) return;
    int src = src_index(j);
    for (int row = row_start + blockIdx.y; row < total_rows; row += gridDim.y) {
        float v = (src >= 0) ? __ldg(hexa + (size_t)row * IN_STRIDE + src) : 0.0f;
        out[(size_t)row * CELLS + j] = v;
    }
}

extern "C" void kernel_launch(void* const* d_in, const int* in_sizes, int n_in,
                              void* d_out, int out_size) {
    const float* hexa = (const float*)d_in[0];
    float* out = (float*)d_out;

    int total_rows = out_size / CELLS;       // 32768
    int n_super = total_rows / 4;            // 8192
    if (n_super > 0) {
        int threads = SLOTS * GROUPS;            // 700,928
        int blocks = (threads + TPB - 1) / TPB;  // 2738
        hexa_direct_kernel<<<blocks, TPB>>>(hexa, out, n_super);
    }
    int done = n_super * 4;
    if (done < total_rows) {
        dim3 grid((CELLS + TPB - 1) / TPB, total_rows - done);
        hexa_tail_kernel<<<grid, TPB>>>(hexa, out, done, total_rows);
    }
}

// round 16
// speedup vs baseline: 1.2066x; 1.0616x over previous
#include <cuda_runtime.h>

// HexaToParallelogram: out[bs, q, r] = hexa[bs, pix(q,r)] for valid hex cells
// (|q+r| <= 18), 0.0 for corner cells. In: [32768, 1039] fp32 (first 1027 used),
// out: [32768, 1369] fp32.
//
// FINAL converged kernel (15 measured rounds). Direct gmem->gmem gather:
// since 1369 % 4 == 1, output float4 alignment repeats every 4 bs-rows
// (supertile = 4*1369 = 5476 floats = 1369 float4s). Each thread owns one
// float4 slot v of the supertile, computes its (row-in-supertile, src, valid)
// tuple ONCE, then grid-strides over supertiles with pure pointer bumps:
//   4 predicated LDG.32 (L1-cached; interleaved-sector loads dedup in L1)
//   1 STG.128 per iteration.
//
// Measured 47.97-55.0 us kernel across identical-code reruns (machine-state
// noise ~±13% on the shared GB300); ~5.5 TB/s effective HBM in good state,
// which is the practical mixed read/write-stream ceiling for this access
// shape. Ablations over cache hints, unroll depth, grid size/shape, iteration
// order, CTA shape, smem staging, swizzles, and load vectorization were all
// within noise or strictly worse.

#define W          37
#define CELLS      1369              // 37*37
#define IN_STRIDE  1039
#define TPB        256
#define SLOTS      1369              // float4 slots per supertile
#define GROUPS     512               // concurrent supertile streams

__device__ __forceinline__ int src_index(int j) {
    int qi = j / W;              // constant divisor -> mulhi
    int ri = j - qi * W;
    int s = qi + ri;
    if (s < 18 || s > 54) return -1;   // padding corner
    if (qi <= 18) {
        return 19 * qi + (qi * (qi - 1)) / 2 + (ri + qi - 18);
    } else {
        int q = qi - 18;
        return 495 + 37 * q - (q * (q - 1)) / 2 + ri;
    }
}

__global__ void __launch_bounds__(TPB)
hexa_direct_kernel(const float* __restrict__ hexa,
                   float* __restrict__ out,
                   int n_super) {
    int t = blockIdx.x * TPB + threadIdx.x;
    if (t >= SLOTS * GROUPS) return;
    int v = t % SLOTS;           // float4 slot within supertile (one-time div)
    int s = t / SLOTS;           // starting supertile
    if (s >= n_super) return;

    // One-time setup: resolve the 4 elements of this slot.
    int f  = 4 * v;              // flat float index in supertile [0, 5476)
    int lr = f / CELLS;          // row within supertile (0..3)
    int j0 = f - lr * CELLS;

    int  off[4];                 // input offset within supertile (floats)
    bool val[4];
    #pragma unroll
    for (int e = 0; e < 4; e++) {
        int j = j0 + e;
        int lrr = lr;
        if (j >= CELLS) { j -= CELLS; lrr++; }
        int src = src_index(j);
        val[e] = (src >= 0);
        off[e] = lrr * IN_STRIDE + (src >= 0 ? src : 0);
    }

    const float* __restrict__ ip = hexa + (size_t)s * (4 * IN_STRIDE);
    float4* __restrict__ op = (float4*)(out + (size_t)s * (4 * CELLS)) + v;

    const size_t ip_step = (size_t)GROUPS * (4 * IN_STRIDE);
    const size_t op_step = (size_t)GROUPS * CELLS;   // in float4s

    #pragma unroll 2
    for (; s < n_super; s += GROUPS) {
        float4 o;
        o.x = val[0] ? __ldg(ip + off[0]) : 0.0f;
        o.y = val[1] ? __ldg(ip + off[1]) : 0.0f;
        o.z = val[2] ? __ldg(ip + off[2]) : 0.0f;
        o.w = val[3] ? __ldg(ip + off[3]) : 0.0f;
        *op = o;
        ip += ip_step;
        op += op_step;
    }
}

// Fallback scalar kernel for any tail rows (total_rows % 4 != 0)
__global__ void __launch_bounds__(TPB)
hexa_tail_kernel(const float* __restrict__ hexa,
                 float* __restrict__ out,
                 int row_start, int total_rows) {
    int j = blockIdx.x * TPB + threadIdx.x;
    if (j >= CELLS) return;
    int src = src_index(j);
    for (int row = row_start + blockIdx.y; row < total_rows; row += gridDim.y) {
        float v = (src >= 0) ? __ldg(hexa + (size_t)row * IN_STRIDE + src) : 0.0f;
        out[(size_t)row * CELLS + j] = v;
    }
}

extern "C" void kernel_launch(void* const* d_in, const int* in_sizes, int n_in,
                              void* d_out, int out_size) {
    const float* hexa = (const float*)d_in[0];
    float* out = (float*)d_out;

    int total_rows = out_size / CELLS;       // 32768
    int n_super = total_rows / 4;            // 8192
    if (n_super > 0) {
        int threads = SLOTS * GROUPS;            // 700,928
        int blocks = (threads + TPB - 1) / TPB;  // 2738
        hexa_direct_kernel<<<blocks, TPB>>>(hexa, out, n_super);
    }
    int done = n_super * 4;
    if (done < total_rows) {
        dim3 grid((CELLS + TPB - 1) / TPB, total_rows - done);
        hexa_tail_kernel<<<grid, TPB>>>(hexa, out, done, total_rows);
    }
}

// round 17
// speedup vs baseline: 1.2163x; 1.0081x over previous
#include <cuda_runtime.h>

// HexaToParallelogram: out[bs, q, r] = hexa[bs, pix(q,r)] for valid hex cells
// (|q+r| <= 18), 0.0 for corner cells. In: [32768, 1039] fp32 (first 1027 used),
// out: [32768, 1369] fp32.
//
// FINAL converged kernel (16 measured rounds). Direct gmem->gmem gather:
// since 1369 % 4 == 1, output float4 alignment repeats every 4 bs-rows
// (supertile = 4*1369 = 5476 floats = 1369 float4s). Each thread owns one
// float4 slot v of the supertile, computes its (row-in-supertile, src, valid)
// tuple ONCE, then grid-strides over supertiles with pure pointer bumps:
//   4 predicated LDG.32 (L1-cached; interleaved-sector loads dedup in L1)
//   1 STG.128 per iteration.
//
// Measured 47.4 / 48.0 / 48.1 / 55.0 us kernel across identical-binary reruns
// (machine-state noise ~±8% on the shared GB300). ~5.55 TB/s effective HBM in
// good state = the practical mixed read/write-stream ceiling for this access
// shape (output rows are sub-128B segments). Traffic is provably minimal: each
// input float read once, each output float written once, no index stream.
// Ablations over cache hints, unroll depth, grid size/shape, iteration order,
// CTA shape, smem staging, swizzles, and load vectorization: all within noise
// or strictly worse.

#define W          37
#define CELLS      1369              // 37*37
#define IN_STRIDE  1039
#define TPB        256
#define SLOTS      1369              // float4 slots per supertile
#define GROUPS     512               // concurrent supertile streams

__device__ __forceinline__ int src_index(int j) {
    int qi = j / W;              // constant divisor -> mulhi
    int ri = j - qi * W;
    int s = qi + ri;
    if (s < 18 || s > 54) return -1;   // padding corner
    if (qi <= 18) {
        return 19 * qi + (qi * (qi - 1)) / 2 + (ri + qi - 18);
    } else {
        int q = qi - 18;
        return 495 + 37 * q - (q * (q - 1)) / 2 + ri;
    }
}

__global__ void __launch_bounds__(TPB)
hexa_direct_kernel(const float* __restrict__ hexa,
                   float* __restrict__ out,
                   int n_super) {
    int t = blockIdx.x * TPB + threadIdx.x;
    if (t >= SLOTS * GROUPS) return;
    int v = t % SLOTS;           // float4 slot within supertile (one-time div)
    int s = t / SLOTS;           // starting supertile
    if (s >= n_super) return;

    // One-time setup: resolve the 4 elements of this slot.
    int f  = 4 * v;              // flat float index in supertile [0, 5476)
    int lr = f / CELLS;          // row within supertile (0..3)
    int j0 = f - lr * CELLS;

    int  off[4];                 // input offset within supertile (floats)
    bool val[4];
    #pragma unroll
    for (int e = 0; e < 4; e++) {
        int j = j0 + e;
        int lrr = lr;
        if (j >= CELLS) { j -= CELLS; lrr++; }
        int src = src_index(j);
        val[e] = (src >= 0);
        off[e] = lrr * IN_STRIDE + (src >= 0 ? src : 0);
    }

    const float* __restrict__ ip = hexa + (size_t)s * (4 * IN_STRIDE);
    float4* __restrict__ op = (float4*)(out + (size_t)s * (4 * CELLS)) + v;

    const size_t ip_step = (size_t)GROUPS * (4 * IN_STRIDE);
    const size_t op_step = (size_t)GROUPS * CELLS;   // in float4s

    #pragma unroll 2
    for (; s < n_super; s += GROUPS) {
        float4 o;
        o.x = val[0] ? __ldg(ip + off[0]) : 0.0f;
        o.y = val[1] ? __ldg(ip + off[1]) : 0.0f;
        o.z = val[2] ? __ldg(ip + off[2]) : 0.0f;
        o.w = val[3] ? __ldg(ip + off[3]) : 0.0f;
        *op = o;
        ip += ip_step;
        op += op_step;
    }
}

// Fallback scalar kernel for any tail rows (total_rows % 4 != 0)
__global__ void __launch_bounds__(TPB)
hexa_tail_kernel(const float* __restrict__ hexa,
                 float* __restrict__ out,
                 int row_start, int total_rows) {
    int j = blockIdx.x * TPB + threadIdx.x;
    if (j >= CELLS) return;
    int src = src_index(j);
    for (int row = row_start + blockIdx.y; row < total_rows; row += gridDim.y) {
        float v = (src >= 0) ? __ldg(hexa + (size_t)row * IN_STRIDE + src) : 0.0f;
        out[(size_t)row * CELLS + j] = v;
    }
}

extern "C" void kernel_launch(void* const* d_in, const int* in_sizes, int n_in,
                              void* d_out, int out_size) {
    const float* hexa = (const float*)d_in[0];
    float* out = (float*)d_out;

    int total_rows = out_size / CELLS;       // 32768
    int n_super = total_rows / 4;            // 8192
    if (n_super > 0) {
        int threads = SLOTS * GROUPS;            // 700,928
        int blocks = (threads + TPB - 1) / TPB;  // 2738
        hexa_direct_kernel<<<blocks, TPB>>>(hexa, out, n_super);
    }
    int done = n_super * 4;
    if (done < total_rows) {
        dim3 grid((CELLS + TPB - 1) / TPB, total_rows - done);
        hexa_tail_kernel<<<grid, TPB>>>(hexa, out, done, total_rows);
    }
}